// round 2
// baseline (speedup 1.0000x reference)
#include <cuda_runtime.h>
#include <cuda_fp16.h>
#include <cstdint>
#include <cstddef>

// ----------------------------------------------------------------------------
// out[16384,4096] = spike[16384,4096] @ W[4096,4096] + bias   (fp32 I/O)
// Harness compiles for plain sm_100 -> no tcgen05 / no wgmma. Use legacy
// mma.sync.m16n8k16 (HMMA) with cp.async 4-stage pipeline, fp32 accum in regs.
// spike is {0,1} -> exact in fp16; W fp16 quantization gives rel_err ~5e-4.
// ----------------------------------------------------------------------------

static constexpr int MM = 16384, KK = 4096, NN = 4096;
static constexpr int BM = 128, BN = 256, BK = 64;
static constexpr int STAGES = 4;
static constexpr int KTILES = KK / BK;          // 64
static constexpr int A_ST = BM * BK * 2;        // 16 KB  (rows of 128 B, SW128)
static constexpr int B_ST = BK * BN * 2;        // 32 KB  (rows of 512 B, custom swz)
static constexpr int STG  = A_ST + B_ST;        // 48 KB
static constexpr int SMEM_BYTES = STAGES * STG; // 192 KB

// fp16 scratch (device globals = allocation-free scratch)
__device__ __align__(128) __half g_S[(size_t)MM * KK];   // 128 MB
__device__ __align__(128) __half g_W[(size_t)KK * NN];   //  32 MB, same [K,N] layout

// ---------------------------------------------------------------- helpers
__device__ __forceinline__ uint32_t smem_u32(const void* p) {
    uint32_t a;
    asm("{ .reg .u64 t; cvta.to.shared.u64 t, %1; cvt.u32.u64 %0, t; }"
        : "=r"(a) : "l"(p));
    return a;
}
__device__ __forceinline__ void cp16(uint32_t dst, const void* src) {
    asm volatile("cp.async.cg.shared.global [%0], [%1], 16;"
                 :: "r"(dst), "l"(src) : "memory");
}
// A tile: 128B rows -> standard SW128 (XOR row%8 into 16B-chunk select)
__device__ __forceinline__ uint32_t swzA(uint32_t off) { return off ^ ((off >> 3) & 0x70); }
// B tile: 512B rows -> XOR k-row%8 (bits 9..11) into 16B-chunk select (bits 4..6)
__device__ __forceinline__ uint32_t swzB(uint32_t off) { return off ^ ((off >> 5) & 0x70); }

#define LDSM4(R, addr)                                                          \
    asm volatile("ldmatrix.sync.aligned.m8n8.x4.shared.b16 {%0,%1,%2,%3}, [%4];"\
                 : "=r"((R)[0]), "=r"((R)[1]), "=r"((R)[2]), "=r"((R)[3])       \
                 : "r"(addr))
#define LDSM4T(R, addr)                                                         \
    asm volatile("ldmatrix.sync.aligned.m8n8.x4.trans.shared.b16 {%0,%1,%2,%3}, [%4];" \
                 : "=r"((R)[0]), "=r"((R)[1]), "=r"((R)[2]), "=r"((R)[3])       \
                 : "r"(addr))
#define MMA16816(C, A, B)                                                       \
    asm volatile("mma.sync.aligned.m16n8k16.row.col.f32.f16.f16.f32 "           \
                 "{%0,%1,%2,%3}, {%4,%5,%6,%7}, {%8,%9}, {%0,%1,%2,%3};"        \
                 : "+f"((C)[0]), "+f"((C)[1]), "+f"((C)[2]), "+f"((C)[3])       \
                 : "r"((A)[0]), "r"((A)[1]), "r"((A)[2]), "r"((A)[3]),          \
                   "r"((B)[0]), "r"((B)[1]))

// ---------------------------------------------------------------- converts
__global__ void cvt_f32_f16(const float4* __restrict__ src, uint2* __restrict__ dst,
                            size_t n4) {
    const size_t stride = (size_t)gridDim.x * blockDim.x;
    for (size_t i = (size_t)blockIdx.x * blockDim.x + threadIdx.x; i < n4; i += stride) {
        float4 v = src[i];
        __half2 a = __floats2half2_rn(v.x, v.y);
        __half2 b = __floats2half2_rn(v.z, v.w);
        uint2 p;
        p.x = *reinterpret_cast<uint32_t*>(&a);
        p.y = *reinterpret_cast<uint32_t*>(&b);
        dst[i] = p;
    }
}

// ---------------------------------------------------------------- GEMM
__global__ void __launch_bounds__(256, 1)
gemm_hmma_kernel(const float* __restrict__ bias, float* __restrict__ out) {
    extern __shared__ __align__(1024) unsigned char smem[];
    const uint32_t sb = smem_u32(smem);

    const int tid = threadIdx.x;
    const int lane = tid & 31;
    const int wid = tid >> 5;
    const int wm = wid >> 2;            // 0..1 : M half (64 rows)
    const int wn = wid & 3;             // 0..3 : N quarter (64 cols)
    const int tile_n = blockIdx.x & 15; // N fastest -> W reused in L2 across wave
    const int tile_m = blockIdx.x >> 4;

    const __half* Ab = g_S + (size_t)(tile_m * BM) * KK;
    const __half* Bb = g_W + tile_n * BN;

    auto load_tile = [&](int s, int t) {
        const uint32_t sa = sb + s * STG;
        const uint32_t sB = sa + A_ST;
        const __half* asrc = Ab + t * BK;
#pragma unroll
        for (int q = 0; q < 4; q++) {                 // A: 128 rows x 8 x 16B
            const int idx = tid + q * 256;
            const int r = idx >> 3, c = idx & 7;
            cp16(sa + swzA((uint32_t)(r * 128 + c * 16)), asrc + (size_t)r * KK + c * 8);
        }
        const __half* bsrc = Bb + (size_t)(t * BK) * NN;
#pragma unroll
        for (int q = 0; q < 8; q++) {                 // B: 64 rows x 32 x 16B
            const int idx = tid + q * 256;
            const int r = idx >> 5, c = idx & 31;
            cp16(sB + swzB((uint32_t)(r * 512 + c * 16)), bsrc + (size_t)r * NN + c * 8);
        }
    };

#pragma unroll
    for (int s = 0; s < STAGES - 1; s++) {
        load_tile(s, s);
        asm volatile("cp.async.commit_group;");
    }

    float acc[4][8][4];
#pragma unroll
    for (int i = 0; i < 4; i++)
#pragma unroll
        for (int j = 0; j < 8; j++)
#pragma unroll
            for (int q = 0; q < 4; q++) acc[i][j][q] = 0.0f;

#pragma unroll 1
    for (int t = 0; t < KTILES; t++) {
        asm volatile("cp.async.wait_group 2;");       // oldest stage complete
        __syncthreads();                              // visible to all warps

        const int tn = t + STAGES - 1;                // refill stage (t-1)%STAGES
        if (tn < KTILES) load_tile(tn % STAGES, tn);
        asm volatile("cp.async.commit_group;");       // commit (possibly empty)

        const uint32_t sa = sb + (t % STAGES) * STG;
        const uint32_t sB = sa + A_ST;
#pragma unroll
        for (int kc = 0; kc < 4; kc++) {              // 4 x k16 per BK=64
            uint32_t a[4][4];
#pragma unroll
            for (int i = 0; i < 4; i++) {             // 4 m16 tiles of this warp
                const int row = wm * 64 + i * 16 + (lane & 15);
                LDSM4(a[i], sa + swzA((uint32_t)(row * 128 + (kc * 2 + (lane >> 4)) * 16)));
            }
            uint32_t b[4][4];
#pragma unroll
            for (int j = 0; j < 4; j++) {             // 4 n16 groups -> 8 n8 tiles
                const int krow = kc * 16 + (lane & 15);
                const int colb = (wn * 64 + j * 16 + (lane >> 4) * 8) * 2;
                LDSM4T(b[j], sB + swzB((uint32_t)(krow * 512 + colb)));
            }
#pragma unroll
            for (int i = 0; i < 4; i++)
#pragma unroll
                for (int jj = 0; jj < 8; jj++)
                    MMA16816(acc[i][jj], a[i], b[jj >> 1] + (jj & 1) * 2);
        }
    }
    asm volatile("cp.async.wait_all;");

    // ---- epilogue: direct stores + bias (each warp owns its 64x64 block)
    float2 bv[8];
#pragma unroll
    for (int jj = 0; jj < 8; jj++)
        bv[jj] = *reinterpret_cast<const float2*>(
            bias + tile_n * 256 + wn * 64 + jj * 8 + (lane & 3) * 2);

#pragma unroll
    for (int i = 0; i < 4; i++) {
        const int r = tile_m * 128 + wm * 64 + i * 16 + (lane >> 2);
        float* o0 = out + (size_t)r * NN + tile_n * 256 + wn * 64 + (lane & 3) * 2;
        float* o1 = o0 + (size_t)8 * NN;
#pragma unroll
        for (int jj = 0; jj < 8; jj++) {
            float2 v0 = { acc[i][jj][0] + bv[jj].x, acc[i][jj][1] + bv[jj].y };
            float2 v1 = { acc[i][jj][2] + bv[jj].x, acc[i][jj][3] + bv[jj].y };
            *reinterpret_cast<float2*>(o0 + jj * 8) = v0;
            *reinterpret_cast<float2*>(o1 + jj * 8) = v1;
        }
    }
}

// ---------------------------------------------------------------- launch
extern "C" void kernel_launch(void* const* d_in, const int* in_sizes, int n_in,
                              void* d_out, int out_size) {
    const float* sparse = (const float*)d_in[0];
    const float* weight = (const float*)d_in[1];
    const float* bias   = (const float*)d_in[2];
    float* out = (float*)d_out;

    cudaFuncSetAttribute(gemm_hmma_kernel,
                         cudaFuncAttributeMaxDynamicSharedMemorySize, SMEM_BYTES);

    __half* dS; cudaGetSymbolAddress((void**)&dS, g_S);
    __half* dW; cudaGetSymbolAddress((void**)&dW, g_W);

    cvt_f32_f16<<<4096, 256>>>(reinterpret_cast<const float4*>(sparse),
                               reinterpret_cast<uint2*>(dS), (size_t)MM * KK / 4);
    cvt_f32_f16<<<2048, 256>>>(reinterpret_cast<const float4*>(weight),
                               reinterpret_cast<uint2*>(dW), (size_t)KK * NN / 4);
    gemm_hmma_kernel<<<(MM / BM) * (NN / BN), 256, SMEM_BYTES>>>(bias, out);
}

// round 3
// speedup vs baseline: 1.0289x; 1.0289x over previous
#include <cuda_runtime.h>
#include <cuda_fp16.h>
#include <cstdint>
#include <cstddef>

// ----------------------------------------------------------------------------
// out[16384,4096] = spike[16384,4096] @ W[4096,4096] + bias   (fp32 I/O)
// sm_100 (no 'a' features) -> legacy mma.sync.m16n8k16 HMMA, cp.async pipeline.
// This round: CUTLASS-style software pipelining — double-buffered register
// fragments + cross-stage fragment prefetch so the tensor pipe never stalls
// on LDS latency or the per-stage syncthreads.
// ----------------------------------------------------------------------------

static constexpr int MM = 16384, KK = 4096, NN = 4096;
static constexpr int BM = 128, BN = 256, BK = 64;
static constexpr int STAGES = 4;
static constexpr int KTILES = KK / BK;          // 64
static constexpr int A_ST = BM * BK * 2;        // 16 KB  (rows of 128 B, SW128)
static constexpr int B_ST = BK * BN * 2;        // 32 KB  (rows of 512 B)
static constexpr int STG  = A_ST + B_ST;        // 48 KB
static constexpr int SMEM_BYTES = STAGES * STG; // 192 KB

__device__ __align__(128) __half g_S[(size_t)MM * KK];   // 128 MB
__device__ __align__(128) __half g_W[(size_t)KK * NN];   //  32 MB  [K,N]

// ---------------------------------------------------------------- helpers
__device__ __forceinline__ uint32_t smem_u32(const void* p) {
    uint32_t a;
    asm("{ .reg .u64 t; cvta.to.shared.u64 t, %1; cvt.u32.u64 %0, t; }"
        : "=r"(a) : "l"(p));
    return a;
}
__device__ __forceinline__ void cp16(uint32_t dst, const void* src) {
    asm volatile("cp.async.cg.shared.global [%0], [%1], 16;"
                 :: "r"(dst), "l"(src) : "memory");
}
__device__ __forceinline__ uint32_t swzA(uint32_t off) { return off ^ ((off >> 3) & 0x70); }
__device__ __forceinline__ uint32_t swzB(uint32_t off) { return off ^ ((off >> 5) & 0x70); }

#define LDSM4(R, addr)                                                          \
    asm volatile("ldmatrix.sync.aligned.m8n8.x4.shared.b16 {%0,%1,%2,%3}, [%4];"\
                 : "=r"((R)[0]), "=r"((R)[1]), "=r"((R)[2]), "=r"((R)[3])       \
                 : "r"(addr))
#define LDSM4T(R, addr)                                                         \
    asm volatile("ldmatrix.sync.aligned.m8n8.x4.trans.shared.b16 {%0,%1,%2,%3}, [%4];" \
                 : "=r"((R)[0]), "=r"((R)[1]), "=r"((R)[2]), "=r"((R)[3])       \
                 : "r"(addr))
#define MMA16816(C, A, B)                                                       \
    asm volatile("mma.sync.aligned.m16n8k16.row.col.f32.f16.f16.f32 "           \
                 "{%0,%1,%2,%3}, {%4,%5,%6,%7}, {%8,%9}, {%0,%1,%2,%3};"        \
                 : "+f"((C)[0]), "+f"((C)[1]), "+f"((C)[2]), "+f"((C)[3])       \
                 : "r"((A)[0]), "r"((A)[1]), "r"((A)[2]), "r"((A)[3]),          \
                   "r"((B)[0]), "r"((B)[1]))

// ---------------------------------------------------------------- converts
__global__ void cvt_f32_f16(const float4* __restrict__ src, uint2* __restrict__ dst,
                            size_t n4) {
    const size_t stride = (size_t)gridDim.x * blockDim.x;
    for (size_t i = (size_t)blockIdx.x * blockDim.x + threadIdx.x; i < n4; i += stride) {
        float4 v = src[i];
        __half2 a = __floats2half2_rn(v.x, v.y);
        __half2 b = __floats2half2_rn(v.z, v.w);
        uint2 p;
        p.x = *reinterpret_cast<uint32_t*>(&a);
        p.y = *reinterpret_cast<uint32_t*>(&b);
        dst[i] = p;
    }
}

// ---------------------------------------------------------------- GEMM
__global__ void __launch_bounds__(256, 1)
gemm_hmma_kernel(const float* __restrict__ bias, float* __restrict__ out) {
    extern __shared__ __align__(1024) unsigned char smem[];
    const uint32_t sb = smem_u32(smem);

    const int tid = threadIdx.x;
    const int lane = tid & 31;
    const int wid = tid >> 5;
    const int wm = wid >> 2;            // 0..1 : M half (64 rows)
    const int wn = wid & 3;             // 0..3 : N quarter (64 cols)
    const int tile_n = blockIdx.x & 15; // N fastest -> W stays L2-resident per wave
    const int tile_m = blockIdx.x >> 4;

    const __half* Ab = g_S + (size_t)(tile_m * BM) * KK;
    const __half* Bb = g_W + tile_n * BN;

    auto load_tile = [&](int s, int t) {
        const uint32_t sa = sb + s * STG;
        const uint32_t sB = sa + A_ST;
        const __half* asrc = Ab + t * BK;
#pragma unroll
        for (int q = 0; q < 4; q++) {                 // A: 128 rows x 8 x 16B
            const int idx = tid + q * 256;
            const int r = idx >> 3, c = idx & 7;
            cp16(sa + swzA((uint32_t)(r * 128 + c * 16)), asrc + (size_t)r * KK + c * 8);
        }
        const __half* bsrc = Bb + (size_t)(t * BK) * NN;
#pragma unroll
        for (int q = 0; q < 8; q++) {                 // B: 64 rows x 32 x 16B
            const int idx = tid + q * 256;
            const int r = idx >> 5, c = idx & 31;
            cp16(sB + swzB((uint32_t)(r * 512 + c * 16)), bsrc + (size_t)r * NN + c * 8);
        }
    };

    // fragment loaders (double-buffered in registers)
    auto load_frag_a = [&](uint32_t a_regs[4][4], uint32_t sa, int kc) {
#pragma unroll
        for (int i = 0; i < 4; i++) {
            const int row = wm * 64 + i * 16 + (lane & 15);
            LDSM4(a_regs[i], sa + swzA((uint32_t)(row * 128 + (kc * 2 + (lane >> 4)) * 16)));
        }
    };
    auto load_frag_b = [&](uint32_t b_regs[4][4], uint32_t sB, int kc) {
#pragma unroll
        for (int j = 0; j < 4; j++) {
            const int krow = kc * 16 + (lane & 15);
            const int colb = (wn * 64 + j * 16 + (lane >> 4) * 8) * 2;
            LDSM4T(b_regs[j], sB + swzB((uint32_t)(krow * 512 + colb)));
        }
    };

    // -------- prologue: fill STAGES-1 pipeline stages
#pragma unroll
    for (int s = 0; s < STAGES - 1; s++) {
        load_tile(s, s);
        asm volatile("cp.async.commit_group;");
    }

    float acc[4][8][4];
#pragma unroll
    for (int i = 0; i < 4; i++)
#pragma unroll
        for (int j = 0; j < 8; j++)
#pragma unroll
            for (int q = 0; q < 4; q++) acc[i][j][q] = 0.0f;

    uint32_t A2[2][4][4], B2[2][4][4];

    asm volatile("cp.async.wait_group 2;");           // stage 0 resident
    __syncthreads();
    {
        const uint32_t sa0 = sb;
        load_frag_a(A2[0], sa0, 0);
        load_frag_b(B2[0], sa0 + A_ST, 0);
    }

#pragma unroll 1
    for (int t = 0; t < KTILES; t++) {
        const uint32_t sa = sb + (t % STAGES) * STG;
        const uint32_t sB = sa + A_ST;
#pragma unroll
        for (int kc = 0; kc < 4; kc++) {
            const int cur = kc & 1;
            const int nxt = cur ^ 1;
            if (kc == 3) {
                // stage transition: make stage t+1 resident, prefetch its kc=0
                if (t + 1 < KTILES) {
                    asm volatile("cp.async.wait_group 2;");
                    __syncthreads();
                    const uint32_t na = sb + ((t + 1) % STAGES) * STG;
                    load_frag_a(A2[nxt], na, 0);
                    load_frag_b(B2[nxt], na + A_ST, 0);
                }
            } else {
                load_frag_a(A2[nxt], sa, kc + 1);
                load_frag_b(B2[nxt], sB, kc + 1);
            }
            // MMAs for kc overlap the prefetch above
#pragma unroll
            for (int i = 0; i < 4; i++)
#pragma unroll
                for (int jj = 0; jj < 8; jj++)
                    MMA16816(acc[i][jj], A2[cur][i], B2[cur][jj >> 1] + (jj & 1) * 2);

            if (kc == 0) {
                // refill the stage freed last transition
                if (t + STAGES - 1 < KTILES) load_tile((t + STAGES - 1) % STAGES, t + STAGES - 1);
                asm volatile("cp.async.commit_group;");
            }
        }
    }
    asm volatile("cp.async.wait_all;");

    // -------- epilogue: direct fp32 stores + bias
    float2 bv[8];
#pragma unroll
    for (int jj = 0; jj < 8; jj++)
        bv[jj] = *reinterpret_cast<const float2*>(
            bias + tile_n * 256 + wn * 64 + jj * 8 + (lane & 3) * 2);

#pragma unroll
    for (int i = 0; i < 4; i++) {
        const int r = tile_m * 128 + wm * 64 + i * 16 + (lane >> 2);
        float* o0 = out + (size_t)r * NN + tile_n * 256 + wn * 64 + (lane & 3) * 2;
        float* o1 = o0 + (size_t)8 * NN;
#pragma unroll
        for (int jj = 0; jj < 8; jj++) {
            float2 v0 = { acc[i][jj][0] + bv[jj].x, acc[i][jj][1] + bv[jj].y };
            float2 v1 = { acc[i][jj][2] + bv[jj].x, acc[i][jj][3] + bv[jj].y };
            *reinterpret_cast<float2*>(o0 + jj * 8) = v0;
            *reinterpret_cast<float2*>(o1 + jj * 8) = v1;
        }
    }
}

// ---------------------------------------------------------------- launch
extern "C" void kernel_launch(void* const* d_in, const int* in_sizes, int n_in,
                              void* d_out, int out_size) {
    const float* sparse = (const float*)d_in[0];
    const float* weight = (const float*)d_in[1];
    const float* bias   = (const float*)d_in[2];
    float* out = (float*)d_out;

    cudaFuncSetAttribute(gemm_hmma_kernel,
                         cudaFuncAttributeMaxDynamicSharedMemorySize, SMEM_BYTES);

    __half* dS; cudaGetSymbolAddress((void**)&dS, g_S);
    __half* dW; cudaGetSymbolAddress((void**)&dW, g_W);

    cvt_f32_f16<<<4096, 256>>>(reinterpret_cast<const float4*>(sparse),
                               reinterpret_cast<uint2*>(dS), (size_t)MM * KK / 4);
    cvt_f32_f16<<<2048, 256>>>(reinterpret_cast<const float4*>(weight),
                               reinterpret_cast<uint2*>(dW), (size_t)KK * NN / 4);
    gemm_hmma_kernel<<<(MM / BM) * (NN / BN), 256, SMEM_BYTES>>>(bias, out);
}